// round 2
// baseline (speedup 1.0000x reference)
#include <cuda_runtime.h>
#include <cstdint>

// PointNet_V3 fused: 3 BN-folded GEMMs + segment sum/max + global max-pool + shuffle.
// Round 2: same design as round 1 (f32x2 SIMT GEMM, smem weights, L2 red epilogue),
// hardened: 16B-aligned scratch for red.v4, input-index autodetect.

#define CIN 16
#define C1  64
#define C2  128
#define SMAX 20000
#define TPB 128

typedef unsigned long long ull;

// ---- persistent device scratch (no allocations allowed) ----
__device__ __align__(16) float    g_W1f [CIN * C1];
__device__ __align__(16) float    g_b1f [C1];
__device__ __align__(16) float    g_W2af[CIN * C2];
__device__ __align__(16) float    g_b2af[C2];
__device__ __align__(16) float    g_W2bf[C2 * C1];
__device__ __align__(16) float    g_b2bf[C1];
__device__ __align__(16) float    g_gsum[SMAX * C1];
__device__ __align__(16) unsigned g_gmax[SMAX * C1];
__device__ __align__(16) unsigned g_pmax[C1];

// ---- f32x2 helpers ----
__device__ __forceinline__ ull pack2(float x, float y) {
    ull r; asm("mov.b64 %0,{%1,%2};" : "=l"(r) : "f"(x), "f"(y)); return r;
}
__device__ __forceinline__ float2 unpack2(ull v) {
    float2 f; asm("mov.b64 {%0,%1},%2;" : "=f"(f.x), "=f"(f.y) : "l"(v)); return f;
}
__device__ __forceinline__ void fma2(ull& d, ull a, ull b) {
    asm("fma.rn.f32x2 %0,%1,%2,%0;" : "+l"(d) : "l"(a), "l"(b));
}
__device__ __forceinline__ void red_add4(float* p, float a, float b, float c, float d) {
    asm volatile("red.global.add.v4.f32 [%0],{%1,%2,%3,%4};"
                 :: "l"(p), "f"(a), "f"(b), "f"(c), "f"(d) : "memory");
}

// ---- fold BN (eval) into weights/bias:  y = x*a + (b - m*a),  a = g/sqrt(v+eps) ----
__global__ void prep_kernel(const float* __restrict__ W1,  const float* __restrict__ g1,
                            const float* __restrict__ b1,  const float* __restrict__ m1,
                            const float* __restrict__ v1,
                            const float* __restrict__ W2a, const float* __restrict__ g2a,
                            const float* __restrict__ b2a, const float* __restrict__ m2a,
                            const float* __restrict__ v2a,
                            const float* __restrict__ W2b, const float* __restrict__ g2b,
                            const float* __restrict__ b2b, const float* __restrict__ m2b,
                            const float* __restrict__ v2b)
{
    __shared__ float a1[C1], a2a[C2], a2b[C1];
    int t = threadIdx.x;
    if (t < C1)  { float a = g1[t]  * rsqrtf(v1[t]  + 1e-3f); a1[t]  = a; g_b1f[t]  = b1[t]  - m1[t]  * a; }
    if (t < C2)  { float a = g2a[t] * rsqrtf(v2a[t] + 1e-3f); a2a[t] = a; g_b2af[t] = b2a[t] - m2a[t] * a; }
    if (t < C1)  { float a = g2b[t] * rsqrtf(v2b[t] + 1e-3f); a2b[t] = a; g_b2bf[t] = b2b[t] - m2b[t] * a; }
    __syncthreads();
    for (int i = t; i < CIN * C1; i += blockDim.x) g_W1f[i]  = W1[i]  * a1[i & (C1 - 1)];
    for (int i = t; i < CIN * C2; i += blockDim.x) g_W2af[i] = W2a[i] * a2a[i & (C2 - 1)];
    for (int i = t; i < C2 * C1;  i += blockDim.x) g_W2bf[i] = W2b[i] * a2b[i & (C1 - 1)];
}

__global__ void init_kernel() {
    int i = blockIdx.x * blockDim.x + threadIdx.x;
    if (i < SMAX * C1) { g_gsum[i] = 0.0f; g_gmax[i] = 0u; }
    if (blockIdx.x == 0 && threadIdx.x < C1) g_pmax[threadIdx.x] = 0u;
}

// smem layout (floats):
//  sW2b[8192] | sW2a[2048] | sW1[1024] | sb2a[128] | sb1[64] | sb2b[64]
//  | hbuf[TPB*33] | inbuf[TPB*17]
#define SMEM_FLOATS (C2*C1 + CIN*C2 + CIN*C1 + C2 + C1 + C1 + TPB*33 + TPB*17)

__global__ __launch_bounds__(TPB) void main_kernel(const float* __restrict__ inp,
                                                   const int* __restrict__ seg, int N)
{
    extern __shared__ float smem[];
    float* sW2b = smem;
    float* sW2a = sW2b + C2 * C1;
    float* sW1  = sW2a + CIN * C2;
    float* sb2a = sW1  + CIN * C1;
    float* sb1  = sb2a + C2;
    float* sb2b = sb1  + C1;
    float* hbuf = sb2b + C1;             // per-thread 32 + 1 pad
    float* inbf = hbuf + TPB * 33;       // per-thread 16 + 1 pad

    const int tid = threadIdx.x;

    // stage folded weights (broadcast-shared by all threads)
    for (int i = tid; i < C2 * C1;  i += TPB) sW2b[i] = g_W2bf[i];
    for (int i = tid; i < CIN * C2; i += TPB) sW2a[i] = g_W2af[i];
    for (int i = tid; i < CIN * C1; i += TPB) sW1[i]  = g_W1f[i];
    if (tid < C2) sb2a[tid] = g_b2af[tid];
    if (tid < C1) { sb1[tid] = g_b1f[tid]; sb2b[tid] = g_b2bf[tid]; }

    // stage this block's input rows, coalesced, padded stride 17
    {
        size_t base = (size_t)blockIdx.x * TPB * CIN;
        size_t total = (size_t)N * CIN;
        for (int i = tid; i < TPB * CIN; i += TPB) {
            size_t g = base + i;
            float v = (g < total) ? inp[g] : 0.0f;
            inbf[(i >> 4) * 17 + (i & 15)] = v;
        }
    }
    __syncthreads();

    const int p = blockIdx.x * TPB + tid;
    const bool active = (p < N);
    const float* myin = inbf + tid * 17;

    // ---------------- branch 1: x = relu(in @ W1f + b1f) ----------------
    ull acc[C1 / 2];
    #pragma unroll
    for (int i = 0; i < C1 / 2; i++) acc[i] = pack2(sb1[2 * i], sb1[2 * i + 1]);
    #pragma unroll 1
    for (int k = 0; k < CIN; k++) {
        ull ak = pack2(myin[k], myin[k]);
        const ulonglong2* w = (const ulonglong2*)(sW1 + k * C1);
        #pragma unroll
        for (int i = 0; i < 16; i++) {
            ulonglong2 ww = w[i];
            fma2(acc[2 * i], ak, ww.x);
            fma2(acc[2 * i + 1], ak, ww.y);
        }
    }
    if (active) {
        int s = seg[p];
        float*    gs = g_gsum + (size_t)s * C1;
        unsigned* gm = g_gmax + (size_t)s * C1;
        #pragma unroll
        for (int i = 0; i < 16; i++) {
            float2 v0 = unpack2(acc[2 * i]);
            float2 v1 = unpack2(acc[2 * i + 1]);
            float a0 = fmaxf(v0.x, 0.0f), a1 = fmaxf(v0.y, 0.0f);
            float a2 = fmaxf(v1.x, 0.0f), a3 = fmaxf(v1.y, 0.0f);
            red_add4(gs + 4 * i, a0, a1, a2, a3);
            atomicMax(gm + 4 * i + 0, __float_as_uint(a0));
            atomicMax(gm + 4 * i + 1, __float_as_uint(a1));
            atomicMax(gm + 4 * i + 2, __float_as_uint(a2));
            atomicMax(gm + 4 * i + 3, __float_as_uint(a3));
        }
    }

    // ------- branch 2: h = relu(in @ W2af + b2af); x2 = relu(h @ W2bf + b2bf) -------
    ull acc2[C1 / 2];
    #pragma unroll
    for (int i = 0; i < C1 / 2; i++) acc2[i] = pack2(sb2b[2 * i], sb2b[2 * i + 1]);

    #pragma unroll 1
    for (int q = 0; q < 4; q++) {                     // 32 h-channels at a time
        ull hacc[16];
        #pragma unroll
        for (int i = 0; i < 16; i++)
            hacc[i] = pack2(sb2a[q * 32 + 2 * i], sb2a[q * 32 + 2 * i + 1]);
        #pragma unroll 1
        for (int k = 0; k < CIN; k++) {
            ull ak = pack2(myin[k], myin[k]);
            const ulonglong2* w = (const ulonglong2*)(sW2a + k * C2 + q * 32);
            #pragma unroll
            for (int i = 0; i < 8; i++) {
                ulonglong2 ww = w[i];
                fma2(hacc[2 * i], ak, ww.x);
                fma2(hacc[2 * i + 1], ak, ww.y);
            }
        }
        float* myh = hbuf + tid * 33;
        #pragma unroll
        for (int i = 0; i < 16; i++) {
            float2 hv = unpack2(hacc[i]);
            myh[2 * i]     = fmaxf(hv.x, 0.0f);
            myh[2 * i + 1] = fmaxf(hv.y, 0.0f);
        }
        #pragma unroll 1
        for (int j = 0; j < 32; j++) {
            float hj = myh[j];
            ull hh = pack2(hj, hj);
            const ulonglong2* w = (const ulonglong2*)(sW2b + (q * 32 + j) * C1);
            #pragma unroll
            for (int i = 0; i < 16; i++) {
                ulonglong2 ww = w[i];
                fma2(acc2[2 * i], hh, ww.x);
                fma2(acc2[2 * i + 1], hh, ww.y);
            }
        }
    }

    // global max-pool over x2: warp redux, lane0 -> L2 red.max
    unsigned lane = tid & 31;
    #pragma unroll
    for (int i = 0; i < C1 / 2; i++) {
        float2 v = unpack2(acc2[i]);
        float v0 = active ? fmaxf(v.x, 0.0f) : 0.0f;
        float v1 = active ? fmaxf(v.y, 0.0f) : 0.0f;
        unsigned m0 = __reduce_max_sync(0xFFFFFFFFu, __float_as_uint(v0));
        unsigned m1 = __reduce_max_sync(0xFFFFFFFFu, __float_as_uint(v1));
        if (lane == 0) {
            atomicMax(&g_pmax[2 * i],     m0);
            atomicMax(&g_pmax[2 * i + 1], m1);
        }
    }
}

// out[s, 3c+0]=sum, out[s, 3c+1]=max, out[s, 3c+2]=pool  (groups=3 channel shuffle)
__global__ void finalize_kernel(float* __restrict__ out, int S) {
    int i = blockIdx.x * blockDim.x + threadIdx.x;
    if (i >= S * C1) return;
    int s = i >> 6, c = i & 63;
    float sum = g_gsum[i];
    float mx  = __uint_as_float(g_gmax[i]);
    float pm  = __uint_as_float(g_pmax[c]);
    float* o = out + (size_t)s * (3 * C1) + c * 3;
    o[0] = sum; o[1] = mx; o[2] = pm;
}

extern "C" void kernel_launch(void* const* d_in, const int* in_sizes, int n_in,
                              void* d_out, int out_size)
{
    const float* inputs = (const float*)d_in[0];
    const int*   unq    = (const int*)  d_in[1];

    // Weight args start at 3 if num_segments is materialized as a size-1 input,
    // at 2 otherwise. W1 has CIN*C1 = 1024 elements; num_segments has 1.
    int base = (in_sizes[2] == 1) ? 3 : 2;

    const float* W1  = (const float*)d_in[base + 0];
    const float* g1  = (const float*)d_in[base + 1];
    const float* b1  = (const float*)d_in[base + 2];
    const float* m1  = (const float*)d_in[base + 3];
    const float* v1  = (const float*)d_in[base + 4];
    const float* W2a = (const float*)d_in[base + 5];
    const float* g2a = (const float*)d_in[base + 6];
    const float* b2a = (const float*)d_in[base + 7];
    const float* m2a = (const float*)d_in[base + 8];
    const float* v2a = (const float*)d_in[base + 9];
    const float* W2b = (const float*)d_in[base + 10];
    const float* g2b = (const float*)d_in[base + 11];
    const float* b2b = (const float*)d_in[base + 12];
    const float* m2b = (const float*)d_in[base + 13];
    const float* v2b = (const float*)d_in[base + 14];

    int N = in_sizes[0] / CIN;
    int S = out_size / (3 * C1);

    size_t smem_bytes = SMEM_FLOATS * sizeof(float);
    cudaFuncSetAttribute(main_kernel, cudaFuncAttributeMaxDynamicSharedMemorySize,
                         (int)smem_bytes);

    prep_kernel<<<1, 256>>>(W1, g1, b1, m1, v1,
                            W2a, g2a, b2a, m2a, v2a,
                            W2b, g2b, b2b, m2b, v2b);
    init_kernel<<<(SMAX * C1 + 255) / 256, 256>>>();
    main_kernel<<<(N + TPB - 1) / TPB, TPB, smem_bytes>>>(inputs, unq, N);
    finalize_kernel<<<(S * C1 + 255) / 256, 256>>>((float*)d_out, S);
}

// round 3
// speedup vs baseline: 1.1588x; 1.1588x over previous
#include <cuda_runtime.h>
#include <cstdint>

// PointNet_V3 fused, round 3:
//   prep  : fold BN into weights (+ packed W1 for the segment kernel)
//   zero  : counts + pool table
//   hist/scan/scatter : counting-sort point ids by segment
//   M2    : branch2 (in->128->64) + global max-pool, register-resident h
//   M1    : warp-per-segment branch1 recompute + sum/max in regs, writes d_out
//           (channel shuffle fused into the store; no table atomics anywhere)

#define CIN 16
#define C1  64
#define C2  128
#define SMAX 20000
#define NMAX 1100000
#define TPB 128

typedef unsigned long long ull;

// ---- persistent device scratch ----
__device__ __align__(16) float    g_W1f [CIN * C1];
__device__ __align__(16) float    g_b1f [C1];
__device__ __align__(16) ull      g_W1p [CIN * 32];   // packed (c, c+32) pairs
__device__ __align__(16) ull      g_b1p [32];
__device__ __align__(16) float    g_W2af[CIN * C2];
__device__ __align__(16) float    g_b2af[C2];
__device__ __align__(16) float    g_W2bf[C2 * C1];
__device__ __align__(16) float    g_b2bf[C1];
__device__ __align__(16) unsigned g_pmax[C1];
__device__ __align__(16) int      g_counts[SMAX + 1];
__device__ __align__(16) int      g_base  [SMAX + 1];
__device__ __align__(16) int      g_work  [SMAX + 1];
__device__ __align__(16) int      g_order [NMAX];

// ---- f32x2 helpers ----
__device__ __forceinline__ ull pack2(float x, float y) {
    ull r; asm("mov.b64 %0,{%1,%2};" : "=l"(r) : "f"(x), "f"(y)); return r;
}
__device__ __forceinline__ float2 unpack2(ull v) {
    float2 f; asm("mov.b64 {%0,%1},%2;" : "=f"(f.x), "=f"(f.y) : "l"(v)); return f;
}
__device__ __forceinline__ void fma2(ull& d, ull a, ull b) {
    asm("fma.rn.f32x2 %0,%1,%2,%0;" : "+l"(d) : "l"(a), "l"(b));
}
__device__ __forceinline__ ull relu2(ull v) {
    float2 f = unpack2(v);
    return pack2(fmaxf(f.x, 0.0f), fmaxf(f.y, 0.0f));
}

// ---- BN fold:  y = x*a + (b - m*a),  a = g/sqrt(v+eps) ----
__global__ void prep_kernel(const float* __restrict__ W1,  const float* __restrict__ g1,
                            const float* __restrict__ b1,  const float* __restrict__ m1,
                            const float* __restrict__ v1,
                            const float* __restrict__ W2a, const float* __restrict__ g2a,
                            const float* __restrict__ b2a, const float* __restrict__ m2a,
                            const float* __restrict__ v2a,
                            const float* __restrict__ W2b, const float* __restrict__ g2b,
                            const float* __restrict__ b2b, const float* __restrict__ m2b,
                            const float* __restrict__ v2b)
{
    __shared__ float a1[C1], a2a[C2], a2b[C1];
    int t = threadIdx.x;
    if (t < C1)  { float a = g1[t]  * rsqrtf(v1[t]  + 1e-3f); a1[t]  = a; g_b1f[t]  = b1[t]  - m1[t]  * a; }
    if (t < C2)  { float a = g2a[t] * rsqrtf(v2a[t] + 1e-3f); a2a[t] = a; g_b2af[t] = b2a[t] - m2a[t] * a; }
    if (t < C1)  { float a = g2b[t] * rsqrtf(v2b[t] + 1e-3f); a2b[t] = a; g_b2bf[t] = b2b[t] - m2b[t] * a; }
    __syncthreads();
    for (int i = t; i < CIN * C1; i += blockDim.x) g_W1f[i]  = W1[i]  * a1[i & (C1 - 1)];
    for (int i = t; i < CIN * C2; i += blockDim.x) g_W2af[i] = W2a[i] * a2a[i & (C2 - 1)];
    for (int i = t; i < C2 * C1;  i += blockDim.x) g_W2bf[i] = W2b[i] * a2b[i & (C1 - 1)];
    __syncthreads();
    if (t < 32) {
        for (int k = 0; k < CIN; k++)
            g_W1p[k * 32 + t] = pack2(g_W1f[k * C1 + t], g_W1f[k * C1 + t + 32]);
        g_b1p[t] = pack2(g_b1f[t], g_b1f[t + 32]);
    }
}

__global__ void zero_kernel(int S) {
    int i = blockIdx.x * blockDim.x + threadIdx.x;
    if (i <= S) g_counts[i] = 0;
    if (i < C1) g_pmax[i] = 0u;
}

__global__ void hist_kernel(const int* __restrict__ seg, int N) {
    int i = blockIdx.x * blockDim.x + threadIdx.x;
    if (i < N) atomicAdd(&g_counts[seg[i]], 1);
}

__global__ void scan_kernel(int S, int N) {      // single block, 1024 threads
    __shared__ int part[1024];
    int t = threadIdx.x;
    int chunk = (S + 1023) >> 10;
    int lo = t * chunk, hi = min(lo + chunk, S);
    int sum = 0;
    for (int i = lo; i < hi; i++) sum += g_counts[i];
    part[t] = sum;
    __syncthreads();
    for (int d = 1; d < 1024; d <<= 1) {
        int v = (t >= d) ? part[t - d] : 0;
        __syncthreads();
        part[t] += v;
        __syncthreads();
    }
    int run = t ? part[t - 1] : 0;
    for (int i = lo; i < hi; i++) {
        int c = g_counts[i];
        g_base[i] = run; g_work[i] = run;
        run += c;
    }
    if (t == 1023) g_base[S] = N;
}

__global__ void scatter_kernel(const int* __restrict__ seg, int N) {
    int i = blockIdx.x * blockDim.x + threadIdx.x;
    if (i < N) {
        int pos = atomicAdd(&g_work[seg[i]], 1);
        g_order[pos] = i;
    }
}

// ================= M2: branch2 + global max-pool =================
// smem: sW2b[8192] | sW2a[2048] | sb2a[128] | sb2b[64] | inbuf[TPB*17]
#define M2_SMEM (C2*C1 + CIN*C2 + C2 + C1 + TPB*17)

__global__ __launch_bounds__(TPB, 4) void branch2_kernel(const float* __restrict__ inp, int N)
{
    extern __shared__ float smem[];
    float* sW2b = smem;
    float* sW2a = sW2b + C2 * C1;
    float* sb2a = sW2a + CIN * C2;
    float* sb2b = sb2a + C2;
    float* inbf = sb2b + C1;

    const int tid = threadIdx.x;

    for (int i = tid; i < C2 * C1;  i += TPB) sW2b[i] = g_W2bf[i];
    for (int i = tid; i < CIN * C2; i += TPB) sW2a[i] = g_W2af[i];
    if (tid < C2) sb2a[tid] = g_b2af[tid];
    if (tid < C1) sb2b[tid] = g_b2bf[tid];

    {
        size_t base = (size_t)blockIdx.x * TPB * CIN;
        size_t total = (size_t)N * CIN;
        for (int i = tid; i < TPB * CIN; i += TPB) {
            size_t g = base + i;
            float v = (g < total) ? inp[g] : 0.0f;
            inbf[(i >> 4) * 17 + (i & 15)] = v;
        }
    }
    __syncthreads();

    const int p = blockIdx.x * TPB + tid;
    const bool active = (p < N);
    const float* myin = inbf + tid * 17;

    ull acc2[C1 / 2];
    #pragma unroll
    for (int i = 0; i < C1 / 2; i++) acc2[i] = pack2(sb2b[2 * i], sb2b[2 * i + 1]);

    #pragma unroll 1
    for (int q = 0; q < 4; q++) {
        // ---- h chunk: 32 channels, kept in registers ----
        ull h[16];
        #pragma unroll
        for (int i = 0; i < 16; i++)
            h[i] = pack2(sb2a[q * 32 + 2 * i], sb2a[q * 32 + 2 * i + 1]);
        #pragma unroll
        for (int k = 0; k < CIN; k++) {
            ull ak = pack2(myin[k], myin[k]);
            const ulonglong2* w = (const ulonglong2*)(sW2a + k * C2 + q * 32);
            #pragma unroll
            for (int i = 0; i < 8; i++) {
                ulonglong2 ww = w[i];
                fma2(h[2 * i], ak, ww.x);
                fma2(h[2 * i + 1], ak, ww.y);
            }
        }
        #pragma unroll
        for (int i = 0; i < 16; i++) h[i] = relu2(h[i]);

        // ---- consume h: fully static register indexing ----
        #pragma unroll
        for (int jj = 0; jj < 16; jj++) {
            float2 hp = unpack2(h[jj]);
            {
                ull hh = pack2(hp.x, hp.x);
                const ulonglong2* w = (const ulonglong2*)(sW2b + (q * 32 + 2 * jj) * C1);
                #pragma unroll
                for (int i = 0; i < 16; i++) {
                    ulonglong2 ww = w[i];
                    fma2(acc2[2 * i], hh, ww.x);
                    fma2(acc2[2 * i + 1], hh, ww.y);
                }
            }
            {
                ull hh = pack2(hp.y, hp.y);
                const ulonglong2* w = (const ulonglong2*)(sW2b + (q * 32 + 2 * jj + 1) * C1);
                #pragma unroll
                for (int i = 0; i < 16; i++) {
                    ulonglong2 ww = w[i];
                    fma2(acc2[2 * i], hh, ww.x);
                    fma2(acc2[2 * i + 1], hh, ww.y);
                }
            }
        }
    }

    // global max-pool: warp redux, lane0 -> L2 atomic (64 addrs only)
    unsigned lane = tid & 31;
    #pragma unroll
    for (int i = 0; i < C1 / 2; i++) {
        float2 v = unpack2(acc2[i]);
        float v0 = active ? fmaxf(v.x, 0.0f) : 0.0f;
        float v1 = active ? fmaxf(v.y, 0.0f) : 0.0f;
        unsigned m0 = __reduce_max_sync(0xFFFFFFFFu, __float_as_uint(v0));
        unsigned m1 = __reduce_max_sync(0xFFFFFFFFu, __float_as_uint(v1));
        if (lane == 0) {
            atomicMax(&g_pmax[2 * i],     m0);
            atomicMax(&g_pmax[2 * i + 1], m1);
        }
    }
}

// ================= M1: warp-per-segment branch1 + reductions =================
#define M1_TPB 256
#define M1_WPB (M1_TPB / 32)

__global__ __launch_bounds__(M1_TPB) void segred_kernel(const float* __restrict__ inp,
                                                        float* __restrict__ out, int S)
{
    __shared__ ull sW[CIN * 32];
    __shared__ ull sB[32];
    int tid = threadIdx.x;
    for (int i = tid; i < CIN * 32; i += M1_TPB) sW[i] = g_W1p[i];
    if (tid < 32) sB[tid] = g_b1p[tid];
    __syncthreads();

    int s = blockIdx.x * M1_WPB + (tid >> 5);
    if (s >= S) return;
    int lane = tid & 31;

    ull w[CIN];
    #pragma unroll
    for (int k = 0; k < CIN; k++) w[k] = sW[k * 32 + lane];
    ull bias = sB[lane];

    int start = g_base[s], end = g_base[s + 1];
    float s0 = 0.0f, s1 = 0.0f, m0 = 0.0f, m1 = 0.0f;

    float vnext = 0.0f;
    if (start < end) {
        int p0 = g_order[start];
        vnext = __ldg(inp + (size_t)p0 * CIN + (lane & 15));
    }
    for (int i = start; i < end; i++) {
        float v = vnext;
        if (i + 1 < end) {
            int pn = g_order[i + 1];
            vnext = __ldg(inp + (size_t)pn * CIN + (lane & 15));
        }
        ull acc = bias;
        #pragma unroll
        for (int k = 0; k < CIN; k++) {
            float bk = __shfl_sync(0xFFFFFFFFu, v, k);
            fma2(acc, pack2(bk, bk), w[k]);
        }
        float2 x = unpack2(acc);
        float a0 = fmaxf(x.x, 0.0f), a1 = fmaxf(x.y, 0.0f);
        s0 += a0; s1 += a1;
        m0 = fmaxf(m0, a0); m1 = fmaxf(m1, a1);
    }

    float p0 = __uint_as_float(g_pmax[lane]);
    float p1 = __uint_as_float(g_pmax[lane + 32]);

    // channel shuffle groups=3: out[s, c*3 + {0:sum, 1:max, 2:pool}]
    float* o = out + (size_t)s * (3 * C1);
    o[lane * 3 + 0] = s0;
    o[lane * 3 + 1] = m0;
    o[lane * 3 + 2] = p0;
    o[(lane + 32) * 3 + 0] = s1;
    o[(lane + 32) * 3 + 1] = m1;
    o[(lane + 32) * 3 + 2] = p1;
}

extern "C" void kernel_launch(void* const* d_in, const int* in_sizes, int n_in,
                              void* d_out, int out_size)
{
    const float* inputs = (const float*)d_in[0];
    const int*   unq    = (const int*)  d_in[1];

    int base = (in_sizes[2] == 1) ? 3 : 2;
    const float* W1  = (const float*)d_in[base + 0];
    const float* g1  = (const float*)d_in[base + 1];
    const float* b1  = (const float*)d_in[base + 2];
    const float* m1  = (const float*)d_in[base + 3];
    const float* v1  = (const float*)d_in[base + 4];
    const float* W2a = (const float*)d_in[base + 5];
    const float* g2a = (const float*)d_in[base + 6];
    const float* b2a = (const float*)d_in[base + 7];
    const float* m2a = (const float*)d_in[base + 8];
    const float* v2a = (const float*)d_in[base + 9];
    const float* W2b = (const float*)d_in[base + 10];
    const float* g2b = (const float*)d_in[base + 11];
    const float* b2b = (const float*)d_in[base + 12];
    const float* m2b = (const float*)d_in[base + 13];
    const float* v2b = (const float*)d_in[base + 14];

    int N = in_sizes[0] / CIN;
    if (N > NMAX) N = NMAX;
    int S = out_size / (3 * C1);
    if (S > SMAX) S = SMAX;

    size_t m2_smem = M2_SMEM * sizeof(float);
    cudaFuncSetAttribute(branch2_kernel, cudaFuncAttributeMaxDynamicSharedMemorySize,
                         (int)m2_smem);

    prep_kernel<<<1, 256>>>(W1, g1, b1, m1, v1,
                            W2a, g2a, b2a, m2a, v2a,
                            W2b, g2b, b2b, m2b, v2b);
    zero_kernel<<<(SMAX + 256) / 256, 256>>>(S);
    hist_kernel<<<(N + 255) / 256, 256>>>(unq, N);
    scan_kernel<<<1, 1024>>>(S, N);
    scatter_kernel<<<(N + 255) / 256, 256>>>(unq, N);
    branch2_kernel<<<(N + TPB - 1) / TPB, TPB, m2_smem>>>(inputs, N);
    segred_kernel<<<(S + M1_WPB - 1) / M1_WPB, M1_TPB>>>(inputs, (float*)d_out, S);
}

// round 4
// speedup vs baseline: 1.1888x; 1.0258x over previous
#include <cuda_runtime.h>
#include <cstdint>

// PointNet_V3 fused, round 4: R3 pipeline, branch2 de-spilled via
// __launch_bounds__(128,3) (170-reg budget for the 96-reg accumulator set),
// warp-shuffle scan.

#define CIN 16
#define C1  64
#define C2  128
#define SMAX 20000
#define NMAX 1100000
#define TPB 128

typedef unsigned long long ull;

// ---- persistent device scratch ----
__device__ __align__(16) float    g_W1f [CIN * C1];
__device__ __align__(16) float    g_b1f [C1];
__device__ __align__(16) ull      g_W1p [CIN * 32];   // packed (c, c+32) pairs
__device__ __align__(16) ull      g_b1p [32];
__device__ __align__(16) float    g_W2af[CIN * C2];
__device__ __align__(16) float    g_b2af[C2];
__device__ __align__(16) float    g_W2bf[C2 * C1];
__device__ __align__(16) float    g_b2bf[C1];
__device__ __align__(16) unsigned g_pmax[C1];
__device__ __align__(16) int      g_counts[SMAX + 1];
__device__ __align__(16) int      g_base  [SMAX + 1];
__device__ __align__(16) int      g_work  [SMAX + 1];
__device__ __align__(16) int      g_order [NMAX];

// ---- f32x2 helpers ----
__device__ __forceinline__ ull pack2(float x, float y) {
    ull r; asm("mov.b64 %0,{%1,%2};" : "=l"(r) : "f"(x), "f"(y)); return r;
}
__device__ __forceinline__ float2 unpack2(ull v) {
    float2 f; asm("mov.b64 {%0,%1},%2;" : "=f"(f.x), "=f"(f.y) : "l"(v)); return f;
}
__device__ __forceinline__ void fma2(ull& d, ull a, ull b) {
    asm("fma.rn.f32x2 %0,%1,%2,%0;" : "+l"(d) : "l"(a), "l"(b));
}
__device__ __forceinline__ ull relu2(ull v) {
    float2 f = unpack2(v);
    return pack2(fmaxf(f.x, 0.0f), fmaxf(f.y, 0.0f));
}

// ---- BN fold:  y = x*a + (b - m*a),  a = g/sqrt(v+eps) ----
__global__ void prep_kernel(const float* __restrict__ W1,  const float* __restrict__ g1,
                            const float* __restrict__ b1,  const float* __restrict__ m1,
                            const float* __restrict__ v1,
                            const float* __restrict__ W2a, const float* __restrict__ g2a,
                            const float* __restrict__ b2a, const float* __restrict__ m2a,
                            const float* __restrict__ v2a,
                            const float* __restrict__ W2b, const float* __restrict__ g2b,
                            const float* __restrict__ b2b, const float* __restrict__ m2b,
                            const float* __restrict__ v2b)
{
    __shared__ float a1[C1], a2a[C2], a2b[C1];
    int t = threadIdx.x;
    if (t < C1)  { float a = g1[t]  * rsqrtf(v1[t]  + 1e-3f); a1[t]  = a; g_b1f[t]  = b1[t]  - m1[t]  * a; }
    if (t < C2)  { float a = g2a[t] * rsqrtf(v2a[t] + 1e-3f); a2a[t] = a; g_b2af[t] = b2a[t] - m2a[t] * a; }
    if (t < C1)  { float a = g2b[t] * rsqrtf(v2b[t] + 1e-3f); a2b[t] = a; g_b2bf[t] = b2b[t] - m2b[t] * a; }
    __syncthreads();
    for (int i = t; i < CIN * C1; i += blockDim.x) g_W1f[i]  = W1[i]  * a1[i & (C1 - 1)];
    for (int i = t; i < CIN * C2; i += blockDim.x) g_W2af[i] = W2a[i] * a2a[i & (C2 - 1)];
    for (int i = t; i < C2 * C1;  i += blockDim.x) g_W2bf[i] = W2b[i] * a2b[i & (C1 - 1)];
    __syncthreads();
    if (t < 32) {
        for (int k = 0; k < CIN; k++)
            g_W1p[k * 32 + t] = pack2(g_W1f[k * C1 + t], g_W1f[k * C1 + t + 32]);
        g_b1p[t] = pack2(g_b1f[t], g_b1f[t + 32]);
    }
}

__global__ void zero_kernel(int S) {
    int i = blockIdx.x * blockDim.x + threadIdx.x;
    if (i <= S) g_counts[i] = 0;
    if (i < C1) g_pmax[i] = 0u;
}

__global__ void hist_kernel(const int* __restrict__ seg, int N) {
    int i = blockIdx.x * blockDim.x + threadIdx.x;
    if (i < N) atomicAdd(&g_counts[seg[i]], 1);
}

// single block, 1024 threads; warp-shuffle scan of the 32 warp partials
__global__ void scan_kernel(int S, int N) {
    __shared__ int wsum[32];
    int t = threadIdx.x;
    int chunk = (S + 1023) >> 10;           // 20 for S=20000
    int lo = t * chunk, hi = min(lo + chunk, S);
    int sum = 0;
    #pragma unroll 4
    for (int i = lo; i < hi; i++) sum += g_counts[i];

    // intra-warp inclusive scan of per-thread sums
    int lane = t & 31, wid = t >> 5;
    int v = sum;
    #pragma unroll
    for (int d = 1; d < 32; d <<= 1) {
        int o = __shfl_up_sync(0xFFFFFFFFu, v, d);
        if (lane >= d) v += o;
    }
    if (lane == 31) wsum[wid] = v;
    __syncthreads();
    if (wid == 0) {
        int w = (lane < 32) ? wsum[lane] : 0;
        #pragma unroll
        for (int d = 1; d < 32; d <<= 1) {
            int o = __shfl_up_sync(0xFFFFFFFFu, w, d);
            if (lane >= d) w += o;
        }
        wsum[lane] = w;
    }
    __syncthreads();
    int excl = v - sum + (wid ? wsum[wid - 1] : 0);   // exclusive prefix of this thread

    int run = excl;
    for (int i = lo; i < hi; i++) {
        int c = g_counts[i];
        g_base[i] = run; g_work[i] = run;
        run += c;
    }
    if (t == 1023) g_base[S] = N;
}

__global__ void scatter_kernel(const int* __restrict__ seg, int N) {
    int i = blockIdx.x * blockDim.x + threadIdx.x;
    if (i < N) {
        int pos = atomicAdd(&g_work[seg[i]], 1);
        g_order[pos] = i;
    }
}

// ================= M2: branch2 + global max-pool =================
// smem: sW2b[8192] | sW2a[2048] | sb2a[128] | sb2b[64] | inbuf[TPB*17]
#define M2_SMEM (C2*C1 + CIN*C2 + C2 + C1 + TPB*17)

__global__ __launch_bounds__(TPB, 3) void branch2_kernel(const float* __restrict__ inp, int N)
{
    extern __shared__ float smem[];
    float* sW2b = smem;
    float* sW2a = sW2b + C2 * C1;
    float* sb2a = sW2a + CIN * C2;
    float* sb2b = sb2a + C2;
    float* inbf = sb2b + C1;

    const int tid = threadIdx.x;

    for (int i = tid; i < C2 * C1;  i += TPB) sW2b[i] = g_W2bf[i];
    for (int i = tid; i < CIN * C2; i += TPB) sW2a[i] = g_W2af[i];
    if (tid < C2) sb2a[tid] = g_b2af[tid];
    if (tid < C1) sb2b[tid] = g_b2bf[tid];

    {
        size_t base = (size_t)blockIdx.x * TPB * CIN;
        size_t total = (size_t)N * CIN;
        for (int i = tid; i < TPB * CIN; i += TPB) {
            size_t g = base + i;
            float v = (g < total) ? inp[g] : 0.0f;
            inbf[(i >> 4) * 17 + (i & 15)] = v;
        }
    }
    __syncthreads();

    const int p = blockIdx.x * TPB + tid;
    const bool active = (p < N);
    const float* myin = inbf + tid * 17;

    ull acc2[C1 / 2];
    #pragma unroll
    for (int i = 0; i < C1 / 2; i++) acc2[i] = pack2(sb2b[2 * i], sb2b[2 * i + 1]);

    #pragma unroll 1
    for (int q = 0; q < 4; q++) {
        // ---- h chunk: 32 channels, kept in registers ----
        ull h[16];
        #pragma unroll
        for (int i = 0; i < 16; i++)
            h[i] = pack2(sb2a[q * 32 + 2 * i], sb2a[q * 32 + 2 * i + 1]);
        #pragma unroll
        for (int k = 0; k < CIN; k++) {
            ull ak = pack2(myin[k], myin[k]);
            const ulonglong2* w = (const ulonglong2*)(sW2a + k * C2 + q * 32);
            #pragma unroll
            for (int i = 0; i < 8; i++) {
                ulonglong2 ww = w[i];
                fma2(h[2 * i], ak, ww.x);
                fma2(h[2 * i + 1], ak, ww.y);
            }
        }
        #pragma unroll
        for (int i = 0; i < 16; i++) h[i] = relu2(h[i]);

        // ---- consume h: fully static register indexing ----
        #pragma unroll
        for (int jj = 0; jj < 16; jj++) {
            float2 hp = unpack2(h[jj]);
            {
                ull hh = pack2(hp.x, hp.x);
                const ulonglong2* w = (const ulonglong2*)(sW2b + (q * 32 + 2 * jj) * C1);
                #pragma unroll
                for (int i = 0; i < 16; i++) {
                    ulonglong2 ww = w[i];
                    fma2(acc2[2 * i], hh, ww.x);
                    fma2(acc2[2 * i + 1], hh, ww.y);
                }
            }
            {
                ull hh = pack2(hp.y, hp.y);
                const ulonglong2* w = (const ulonglong2*)(sW2b + (q * 32 + 2 * jj + 1) * C1);
                #pragma unroll
                for (int i = 0; i < 16; i++) {
                    ulonglong2 ww = w[i];
                    fma2(acc2[2 * i], hh, ww.x);
                    fma2(acc2[2 * i + 1], hh, ww.y);
                }
            }
        }
    }

    // global max-pool: warp redux, lane0 -> L2 atomic (64 addrs only)
    unsigned lane = tid & 31;
    #pragma unroll
    for (int i = 0; i < C1 / 2; i++) {
        float2 v = unpack2(acc2[i]);
        float v0 = active ? fmaxf(v.x, 0.0f) : 0.0f;
        float v1 = active ? fmaxf(v.y, 0.0f) : 0.0f;
        unsigned m0 = __reduce_max_sync(0xFFFFFFFFu, __float_as_uint(v0));
        unsigned m1 = __reduce_max_sync(0xFFFFFFFFu, __float_as_uint(v1));
        if (lane == 0) {
            atomicMax(&g_pmax[2 * i],     m0);
            atomicMax(&g_pmax[2 * i + 1], m1);
        }
    }
}

// ================= M1: warp-per-segment branch1 + reductions =================
#define M1_TPB 256
#define M1_WPB (M1_TPB / 32)

__global__ __launch_bounds__(M1_TPB) void segred_kernel(const float* __restrict__ inp,
                                                        float* __restrict__ out, int S)
{
    __shared__ ull sW[CIN * 32];
    __shared__ ull sB[32];
    int tid = threadIdx.x;
    for (int i = tid; i < CIN * 32; i += M1_TPB) sW[i] = g_W1p[i];
    if (tid < 32) sB[tid] = g_b1p[tid];
    __syncthreads();

    int s = blockIdx.x * M1_WPB + (tid >> 5);
    if (s >= S) return;
    int lane = tid & 31;

    ull w[CIN];
    #pragma unroll
    for (int k = 0; k < CIN; k++) w[k] = sW[k * 32 + lane];
    ull bias = sB[lane];

    int start = g_base[s], end = g_base[s + 1];
    float s0 = 0.0f, s1 = 0.0f, m0 = 0.0f, m1 = 0.0f;

    float vnext = 0.0f;
    if (start < end) {
        int p0 = g_order[start];
        vnext = __ldg(inp + (size_t)p0 * CIN + (lane & 15));
    }
    for (int i = start; i < end; i++) {
        float v = vnext;
        if (i + 1 < end) {
            int pn = g_order[i + 1];
            vnext = __ldg(inp + (size_t)pn * CIN + (lane & 15));
        }
        ull acc = bias;
        #pragma unroll
        for (int k = 0; k < CIN; k++) {
            float bk = __shfl_sync(0xFFFFFFFFu, v, k);
            fma2(acc, pack2(bk, bk), w[k]);
        }
        float2 x = unpack2(acc);
        float a0 = fmaxf(x.x, 0.0f), a1 = fmaxf(x.y, 0.0f);
        s0 += a0; s1 += a1;
        m0 = fmaxf(m0, a0); m1 = fmaxf(m1, a1);
    }

    float p0 = __uint_as_float(g_pmax[lane]);
    float p1 = __uint_as_float(g_pmax[lane + 32]);

    // channel shuffle groups=3: out[s, c*3 + {0:sum, 1:max, 2:pool}]
    float* o = out + (size_t)s * (3 * C1);
    o[lane * 3 + 0] = s0;
    o[lane * 3 + 1] = m0;
    o[lane * 3 + 2] = p0;
    o[(lane + 32) * 3 + 0] = s1;
    o[(lane + 32) * 3 + 1] = m1;
    o[(lane + 32) * 3 + 2] = p1;
}

extern "C" void kernel_launch(void* const* d_in, const int* in_sizes, int n_in,
                              void* d_out, int out_size)
{
    const float* inputs = (const float*)d_in[0];
    const int*   unq    = (const int*)  d_in[1];

    int base = (in_sizes[2] == 1) ? 3 : 2;
    const float* W1  = (const float*)d_in[base + 0];
    const float* g1  = (const float*)d_in[base + 1];
    const float* b1  = (const float*)d_in[base + 2];
    const float* m1  = (const float*)d_in[base + 3];
    const float* v1  = (const float*)d_in[base + 4];
    const float* W2a = (const float*)d_in[base + 5];
    const float* g2a = (const float*)d_in[base + 6];
    const float* b2a = (const float*)d_in[base + 7];
    const float* m2a = (const float*)d_in[base + 8];
    const float* v2a = (const float*)d_in[base + 9];
    const float* W2b = (const float*)d_in[base + 10];
    const float* g2b = (const float*)d_in[base + 11];
    const float* b2b = (const float*)d_in[base + 12];
    const float* m2b = (const float*)d_in[base + 13];
    const float* v2b = (const float*)d_in[base + 14];

    int N = in_sizes[0] / CIN;
    if (N > NMAX) N = NMAX;
    int S = out_size / (3 * C1);
    if (S > SMAX) S = SMAX;

    size_t m2_smem = M2_SMEM * sizeof(float);
    cudaFuncSetAttribute(branch2_kernel, cudaFuncAttributeMaxDynamicSharedMemorySize,
                         (int)m2_smem);

    prep_kernel<<<1, 256>>>(W1, g1, b1, m1, v1,
                            W2a, g2a, b2a, m2a, v2a,
                            W2b, g2b, b2b, m2b, v2b);
    zero_kernel<<<(SMAX + 256) / 256, 256>>>(S);
    hist_kernel<<<(N + 255) / 256, 256>>>(unq, N);
    scan_kernel<<<1, 1024>>>(S, N);
    scatter_kernel<<<(N + 255) / 256, 256>>>(unq, N);
    branch2_kernel<<<(N + TPB - 1) / TPB, TPB, m2_smem>>>(inputs, N);
    segred_kernel<<<(S + M1_WPB - 1) / M1_WPB, M1_TPB>>>(inputs, (float*)d_out, S);
}

// round 6
// speedup vs baseline: 1.1953x; 1.0055x over previous
#include <cuda_runtime.h>
#include <cstdint>

// PointNet_V3 fused, round 6 (= round 5 resubmit; R5 died to infra, not kernel):
//  - branch2 split into two 32-channel passes (recompute h) -> ~110 live regs,
//    launch_bounds(128,4) => 16 warps/SM
//  - launch order puts branch2 at index 3 so ncu (-s 5) captures it
//  - scan loads vectorized (int4)

#define CIN 16
#define C1  64
#define C2  128
#define SMAX 20000
#define NMAX 1100000
#define TPB 128

typedef unsigned long long ull;

// ---- persistent device scratch ----
__device__ __align__(16) float    g_W1f [CIN * C1];
__device__ __align__(16) float    g_b1f [C1];
__device__ __align__(16) ull      g_W1p [CIN * 32];   // packed (c, c+32) pairs
__device__ __align__(16) ull      g_b1p [32];
__device__ __align__(16) float    g_W2af[CIN * C2];
__device__ __align__(16) float    g_b2af[C2];
__device__ __align__(16) float    g_W2bf[C2 * C1];
__device__ __align__(16) float    g_b2bf[C1];
__device__ __align__(16) unsigned g_pmax[C1];
__device__ __align__(16) int      g_counts[SMAX + 16];
__device__ __align__(16) int      g_base  [SMAX + 1];
__device__ __align__(16) int      g_work  [SMAX + 1];
__device__ __align__(16) int      g_order [NMAX];

// ---- f32x2 helpers ----
__device__ __forceinline__ ull pack2(float x, float y) {
    ull r; asm("mov.b64 %0,{%1,%2};" : "=l"(r) : "f"(x), "f"(y)); return r;
}
__device__ __forceinline__ float2 unpack2(ull v) {
    float2 f; asm("mov.b64 {%0,%1},%2;" : "=f"(f.x), "=f"(f.y) : "l"(v)); return f;
}
__device__ __forceinline__ void fma2(ull& d, ull a, ull b) {
    asm("fma.rn.f32x2 %0,%1,%2,%0;" : "+l"(d) : "l"(a), "l"(b));
}
__device__ __forceinline__ ull relu2(ull v) {
    float2 f = unpack2(v);
    return pack2(fmaxf(f.x, 0.0f), fmaxf(f.y, 0.0f));
}

// ---- BN fold:  y = x*a + (b - m*a),  a = g/sqrt(v+eps) ----
__global__ void prep_kernel(const float* __restrict__ W1,  const float* __restrict__ g1,
                            const float* __restrict__ b1,  const float* __restrict__ m1,
                            const float* __restrict__ v1,
                            const float* __restrict__ W2a, const float* __restrict__ g2a,
                            const float* __restrict__ b2a, const float* __restrict__ m2a,
                            const float* __restrict__ v2a,
                            const float* __restrict__ W2b, const float* __restrict__ g2b,
                            const float* __restrict__ b2b, const float* __restrict__ m2b,
                            const float* __restrict__ v2b)
{
    __shared__ float a1[C1], a2a[C2], a2b[C1];
    int t = threadIdx.x;
    if (t < C1)  { float a = g1[t]  * rsqrtf(v1[t]  + 1e-3f); a1[t]  = a; g_b1f[t]  = b1[t]  - m1[t]  * a; }
    if (t < C2)  { float a = g2a[t] * rsqrtf(v2a[t] + 1e-3f); a2a[t] = a; g_b2af[t] = b2a[t] - m2a[t] * a; }
    if (t < C1)  { float a = g2b[t] * rsqrtf(v2b[t] + 1e-3f); a2b[t] = a; g_b2bf[t] = b2b[t] - m2b[t] * a; }
    __syncthreads();
    for (int i = t; i < CIN * C1; i += blockDim.x) g_W1f[i]  = W1[i]  * a1[i & (C1 - 1)];
    for (int i = t; i < CIN * C2; i += blockDim.x) g_W2af[i] = W2a[i] * a2a[i & (C2 - 1)];
    for (int i = t; i < C2 * C1;  i += blockDim.x) g_W2bf[i] = W2b[i] * a2b[i & (C1 - 1)];
    __syncthreads();
    if (t < 32) {
        for (int k = 0; k < CIN; k++)
            g_W1p[k * 32 + t] = pack2(g_W1f[k * C1 + t], g_W1f[k * C1 + t + 32]);
        g_b1p[t] = pack2(g_b1f[t], g_b1f[t + 32]);
    }
}

__global__ void zero_kernel(int S) {
    int i = blockIdx.x * blockDim.x + threadIdx.x;
    if (i < SMAX + 16) g_counts[i] = 0;
    if (i < C1) g_pmax[i] = 0u;
}

__global__ void hist_kernel(const int* __restrict__ seg, int N) {
    int i = blockIdx.x * blockDim.x + threadIdx.x;
    if (i < N) atomicAdd(&g_counts[seg[i]], 1);
}

// single block, 1024 threads; int4 loads + warp-shuffle scan
__global__ void scan_kernel(int S, int N) {
    __shared__ int wsum[32];
    int t = threadIdx.x;
    int chunk = (S + 1023) >> 10;
    chunk = (chunk + 3) & ~3;               // multiple of 4 for int4
    int lo = t * chunk;
    int sum = 0;
    const int4* c4 = (const int4*)g_counts;
    if (lo < S) {
        int hi4 = (min(lo + chunk, S) + 3) >> 2;
        for (int i = lo >> 2; i < hi4; i++) {
            int4 v = c4[i];
            sum += v.x + v.y + v.z + v.w;   // out-of-range entries are zero-padded
        }
    }

    int lane = t & 31, wid = t >> 5;
    int v = sum;
    #pragma unroll
    for (int d = 1; d < 32; d <<= 1) {
        int o = __shfl_up_sync(0xFFFFFFFFu, v, d);
        if (lane >= d) v += o;
    }
    if (lane == 31) wsum[wid] = v;
    __syncthreads();
    if (wid == 0) {
        int w = wsum[lane];
        #pragma unroll
        for (int d = 1; d < 32; d <<= 1) {
            int o = __shfl_up_sync(0xFFFFFFFFu, w, d);
            if (lane >= d) w += o;
        }
        wsum[lane] = w;
    }
    __syncthreads();
    int run = v - sum + (wid ? wsum[wid - 1] : 0);

    int hi = min(lo + chunk, S);
    for (int i = lo; i < hi; i++) {
        int c = g_counts[i];
        g_base[i] = run; g_work[i] = run;
        run += c;
    }
    if (t == 1023) g_base[S] = N;
}

__global__ void scatter_kernel(const int* __restrict__ seg, int N) {
    int i = blockIdx.x * blockDim.x + threadIdx.x;
    if (i < N) {
        int pos = atomicAdd(&g_work[seg[i]], 1);
        g_order[pos] = i;
    }
}

// ================= M2: branch2 + global max-pool =================
// smem: sW2b[8192] | sW2a[2048] | sb2a[128] | sb2b[64] | inbuf[TPB*17]
#define M2_SMEM (C2*C1 + CIN*C2 + C2 + C1 + TPB*17)

__global__ __launch_bounds__(TPB, 4) void branch2_kernel(const float* __restrict__ inp, int N)
{
    extern __shared__ float smem[];
    float* sW2b = smem;
    float* sW2a = sW2b + C2 * C1;
    float* sb2a = sW2a + CIN * C2;
    float* sb2b = sb2a + C2;
    float* inbf = sb2b + C1;

    const int tid = threadIdx.x;

    for (int i = tid; i < C2 * C1;  i += TPB) sW2b[i] = g_W2bf[i];
    for (int i = tid; i < CIN * C2; i += TPB) sW2a[i] = g_W2af[i];
    if (tid < C2) sb2a[tid] = g_b2af[tid];
    if (tid < C1) sb2b[tid] = g_b2bf[tid];

    {
        size_t base = (size_t)blockIdx.x * TPB * CIN;
        size_t total = (size_t)N * CIN;
        for (int i = tid; i < TPB * CIN; i += TPB) {
            size_t g = base + i;
            float v = (g < total) ? inp[g] : 0.0f;
            inbf[(i >> 4) * 17 + (i & 15)] = v;
        }
    }
    __syncthreads();

    const int p = blockIdx.x * TPB + tid;
    const bool active = (p < N);
    const float* myin = inbf + tid * 17;
    const unsigned lane = tid & 31;

    // two passes over output-channel halves: 16 acc ull each, h recomputed
    #pragma unroll 1
    for (int pass = 0; pass < 2; pass++) {
        const int cbase = pass * 32;
        ull acc[16];
        #pragma unroll
        for (int i = 0; i < 16; i++)
            acc[i] = pack2(sb2b[cbase + 2 * i], sb2b[cbase + 2 * i + 1]);

        #pragma unroll 1
        for (int q = 0; q < 4; q++) {
            // ---- h chunk: 32 channels in registers ----
            ull h[16];
            #pragma unroll
            for (int i = 0; i < 16; i++)
                h[i] = pack2(sb2a[q * 32 + 2 * i], sb2a[q * 32 + 2 * i + 1]);
            #pragma unroll
            for (int k = 0; k < CIN; k++) {
                ull ak = pack2(myin[k], myin[k]);
                const ulonglong2* w = (const ulonglong2*)(sW2a + k * C2 + q * 32);
                #pragma unroll
                for (int i = 0; i < 8; i++) {
                    ulonglong2 ww = w[i];
                    fma2(h[2 * i], ak, ww.x);
                    fma2(h[2 * i + 1], ak, ww.y);
                }
            }
            #pragma unroll
            for (int i = 0; i < 16; i++) h[i] = relu2(h[i]);

            // ---- consume h into this pass's 32 channels ----
            #pragma unroll
            for (int jj = 0; jj < 16; jj++) {
                float2 hp = unpack2(h[jj]);
                {
                    ull hh = pack2(hp.x, hp.x);
                    const ulonglong2* w = (const ulonglong2*)(sW2b + (q * 32 + 2 * jj) * C1 + cbase);
                    #pragma unroll
                    for (int i = 0; i < 8; i++) {
                        ulonglong2 ww = w[i];
                        fma2(acc[2 * i], hh, ww.x);
                        fma2(acc[2 * i + 1], hh, ww.y);
                    }
                }
                {
                    ull hh = pack2(hp.y, hp.y);
                    const ulonglong2* w = (const ulonglong2*)(sW2b + (q * 32 + 2 * jj + 1) * C1 + cbase);
                    #pragma unroll
                    for (int i = 0; i < 8; i++) {
                        ulonglong2 ww = w[i];
                        fma2(acc[2 * i], hh, ww.x);
                        fma2(acc[2 * i + 1], hh, ww.y);
                    }
                }
            }
        }

        // max-pool epilogue for this half
        #pragma unroll
        for (int i = 0; i < 16; i++) {
            float2 v = unpack2(acc[i]);
            float v0 = active ? fmaxf(v.x, 0.0f) : 0.0f;
            float v1 = active ? fmaxf(v.y, 0.0f) : 0.0f;
            unsigned m0 = __reduce_max_sync(0xFFFFFFFFu, __float_as_uint(v0));
            unsigned m1 = __reduce_max_sync(0xFFFFFFFFu, __float_as_uint(v1));
            if (lane == 0) {
                atomicMax(&g_pmax[cbase + 2 * i],     m0);
                atomicMax(&g_pmax[cbase + 2 * i + 1], m1);
            }
        }
    }
}

// ================= M1: warp-per-segment branch1 + reductions =================
#define M1_TPB 256
#define M1_WPB (M1_TPB / 32)

__global__ __launch_bounds__(M1_TPB) void segred_kernel(const float* __restrict__ inp,
                                                        float* __restrict__ out, int S)
{
    __shared__ ull sW[CIN * 32];
    __shared__ ull sB[32];
    int tid = threadIdx.x;
    for (int i = tid; i < CIN * 32; i += M1_TPB) sW[i] = g_W1p[i];
    if (tid < 32) sB[tid] = g_b1p[tid];
    __syncthreads();

    int s = blockIdx.x * M1_WPB + (tid >> 5);
    if (s >= S) return;
    int lane = tid & 31;

    ull w[CIN];
    #pragma unroll
    for (int k = 0; k < CIN; k++) w[k] = sW[k * 32 + lane];
    ull bias = sB[lane];

    int start = g_base[s], end = g_base[s + 1];
    float s0 = 0.0f, s1 = 0.0f, m0 = 0.0f, m1 = 0.0f;

    float vnext = 0.0f;
    if (start < end) {
        int p0 = g_order[start];
        vnext = __ldg(inp + (size_t)p0 * CIN + (lane & 15));
    }
    for (int i = start; i < end; i++) {
        float v = vnext;
        if (i + 1 < end) {
            int pn = g_order[i + 1];
            vnext = __ldg(inp + (size_t)pn * CIN + (lane & 15));
        }
        ull acc = bias;
        #pragma unroll
        for (int k = 0; k < CIN; k++) {
            float bk = __shfl_sync(0xFFFFFFFFu, v, k);
            fma2(acc, pack2(bk, bk), w[k]);
        }
        float2 x = unpack2(acc);
        float a0 = fmaxf(x.x, 0.0f), a1 = fmaxf(x.y, 0.0f);
        s0 += a0; s1 += a1;
        m0 = fmaxf(m0, a0); m1 = fmaxf(m1, a1);
    }

    float p0 = __uint_as_float(g_pmax[lane]);
    float p1 = __uint_as_float(g_pmax[lane + 32]);

    // channel shuffle groups=3: out[s, c*3 + {0:sum, 1:max, 2:pool}]
    float* o = out + (size_t)s * (3 * C1);
    o[lane * 3 + 0] = s0;
    o[lane * 3 + 1] = m0;
    o[lane * 3 + 2] = p0;
    o[(lane + 32) * 3 + 0] = s1;
    o[(lane + 32) * 3 + 1] = m1;
    o[(lane + 32) * 3 + 2] = p1;
}

extern "C" void kernel_launch(void* const* d_in, const int* in_sizes, int n_in,
                              void* d_out, int out_size)
{
    const float* inputs = (const float*)d_in[0];
    const int*   unq    = (const int*)  d_in[1];

    int base = (in_sizes[2] == 1) ? 3 : 2;
    const float* W1  = (const float*)d_in[base + 0];
    const float* g1  = (const float*)d_in[base + 1];
    const float* b1  = (const float*)d_in[base + 2];
    const float* m1  = (const float*)d_in[base + 3];
    const float* v1  = (const float*)d_in[base + 4];
    const float* W2a = (const float*)d_in[base + 5];
    const float* g2a = (const float*)d_in[base + 6];
    const float* b2a = (const float*)d_in[base + 7];
    const float* m2a = (const float*)d_in[base + 8];
    const float* v2a = (const float*)d_in[base + 9];
    const float* W2b = (const float*)d_in[base + 10];
    const float* g2b = (const float*)d_in[base + 11];
    const float* b2b = (const float*)d_in[base + 12];
    const float* m2b = (const float*)d_in[base + 13];
    const float* v2b = (const float*)d_in[base + 14];

    int N = in_sizes[0] / CIN;
    if (N > NMAX) N = NMAX;
    int S = out_size / (3 * C1);
    if (S > SMAX) S = SMAX;

    size_t m2_smem = M2_SMEM * sizeof(float);
    cudaFuncSetAttribute(branch2_kernel, cudaFuncAttributeMaxDynamicSharedMemorySize,
                         (int)m2_smem);

    prep_kernel<<<1, 256>>>(W1, g1, b1, m1, v1,
                            W2a, g2a, b2a, m2a, v2a,
                            W2b, g2b, b2b, m2b, v2b);
    zero_kernel<<<(SMAX + 256 + 16) / 256, 256>>>(S);
    hist_kernel<<<(N + 255) / 256, 256>>>(unq, N);
    branch2_kernel<<<(N + TPB - 1) / TPB, TPB, m2_smem>>>(inputs, N);   // idx 3: profiled
    scan_kernel<<<1, 1024>>>(S, N);
    scatter_kernel<<<(N + 255) / 256, 256>>>(unq, N);
    segred_kernel<<<(S + M1_WPB - 1) / M1_WPB, M1_TPB>>>(inputs, (float*)d_out, S);
}